// round 4
// baseline (speedup 1.0000x reference)
#include <cuda_runtime.h>
#include <stdint.h>

// Problem constants (fixed by the dataset)
#define NN 100000      // nodes
#define EE 1600000     // edges
#define F0 128
#define F1 64
#define F2 40

// ---------------- scratch (static device globals; allocation-free) ----------
__device__ __align__(16) float g_h1  [NN * F1];   // 25.6 MB  (x @ W1)
__device__ __align__(16) float g_out1[NN * F1];   // 25.6 MB  (relu(agg1 + self))
__device__ __align__(16) float g_h2  [NN * F2];   // 16 MB    (out1 @ W2)
__device__ int   g_deg[NN];
__device__ int   g_off[NN + 1];
__device__ int   g_cursor[NN];
__device__ int   g_csr_src[EE];                   // 6.4 MB, edge srcs grouped by dst
__device__ float g_invsqrt[NN];

// ---------------- kernels ---------------------------------------------------

// Zero degree counters only (no big agg buffers anymore).
__global__ void zero_kernel() {
    int i = blockIdx.x * blockDim.x + threadIdx.x;
    if (i < NN) g_deg[i] = 0;
}

// Degree histogram over dst (self-loop handled as +1 later).
__global__ void deg_kernel(const int* __restrict__ dst, int E) {
    int i = blockIdx.x * blockDim.x + threadIdx.x;
    if (i < E) atomicAdd(&g_deg[dst[i]], 1);
}

// Single-block exclusive prefix scan of g_deg -> g_off / g_cursor.
// 1024 threads, each owns a contiguous chunk of ~98 nodes.
__global__ __launch_bounds__(1024) void prefix_kernel() {
    __shared__ int ssum[1024];
    const int CH = (NN + 1023) / 1024;   // 98
    int t = threadIdx.x;
    int b = t * CH;
    int e = b + CH < NN ? b + CH : NN;

    int s = 0;
    for (int i = b; i < e; ++i) s += g_deg[i];
    ssum[t] = s;
    __syncthreads();

    // inclusive Hillis-Steele scan over 1024 partials
    for (int off = 1; off < 1024; off <<= 1) {
        int v = (t >= off) ? ssum[t - off] : 0;
        __syncthreads();
        ssum[t] += v;
        __syncthreads();
    }

    int run = ssum[t] - s;               // exclusive start of this chunk
    for (int i = b; i < e; ++i) {
        g_off[i]    = run;
        g_cursor[i] = run;
        run += g_deg[i];
    }
    if (e == NN && b < NN) g_off[NN] = run;   // total = E (last active thread)
    if (t == 1023) g_off[NN] = ssum[1023];    // also correct when chunk empty
}

// Fill CSR: group edge srcs by dst via cursor atomics.
__global__ void fill_kernel(const int* __restrict__ src,
                            const int* __restrict__ dst, int E) {
    int i = blockIdx.x * blockDim.x + threadIdx.x;
    if (i < E) {
        int d = dst[i];
        int pos = atomicAdd(&g_cursor[d], 1);
        g_csr_src[pos] = src[i];
    }
}

__global__ void invsqrt_kernel() {
    int i = blockIdx.x * blockDim.x + threadIdx.x;
    if (i < NN) {
        g_invsqrt[i] = rsqrtf((float)(g_deg[i] + 1));
    }
}

// h1 = x @ W1  (100000x128 @ 128x64), fp32.
// Block: 128 threads = 32 row-groups x 4 col-groups. Thread computes 4 rows x 16 cols.
__global__ __launch_bounds__(128) void gemm1_kernel(const float* __restrict__ x,
                                                    const float* __restrict__ W1) {
    __shared__ float sW[F0 * F1];           // 32 KB
    int tid = threadIdx.x;
    for (int i = tid; i < F0 * F1; i += 128) sW[i] = W1[i];
    __syncthreads();

    int rg = tid & 31;                      // row group within block
    int cg = tid >> 5;                      // col group (warp id): cols cg*16..+15
    int row0 = blockIdx.x * 128 + rg * 4;
    int c0 = cg * 16;

    float acc[4][16];
    #pragma unroll
    for (int r = 0; r < 4; ++r)
        #pragma unroll
        for (int j = 0; j < 16; ++j) acc[r][j] = 0.f;

    // clamp rows for loads (stores are guarded)
    const float4* xr[4];
    #pragma unroll
    for (int r = 0; r < 4; ++r) {
        int rr = row0 + r; if (rr >= NN) rr = NN - 1;
        xr[r] = reinterpret_cast<const float4*>(x + (size_t)rr * F0);
    }

    #pragma unroll 4
    for (int k4 = 0; k4 < F0 / 4; ++k4) {
        float4 xv[4];
        #pragma unroll
        for (int r = 0; r < 4; ++r) xv[r] = xr[r][k4];
        #pragma unroll
        for (int kk = 0; kk < 4; ++kk) {
            const float4* w4 = reinterpret_cast<const float4*>(sW + (k4 * 4 + kk) * F1 + c0);
            float4 w0 = w4[0], w1 = w4[1], w2 = w4[2], w3 = w4[3];
            float wv[16] = {w0.x,w0.y,w0.z,w0.w, w1.x,w1.y,w1.z,w1.w,
                            w2.x,w2.y,w2.z,w2.w, w3.x,w3.y,w3.z,w3.w};
            #pragma unroll
            for (int r = 0; r < 4; ++r) {
                float xs = (kk == 0) ? xv[r].x : (kk == 1) ? xv[r].y
                         : (kk == 2) ? xv[r].z : xv[r].w;
                #pragma unroll
                for (int j = 0; j < 16; ++j)
                    acc[r][j] = fmaf(xs, wv[j], acc[r][j]);
            }
        }
    }

    #pragma unroll
    for (int r = 0; r < 4; ++r) {
        int rr = row0 + r;
        if (rr < NN) {
            float4* out = reinterpret_cast<float4*>(g_h1 + (size_t)rr * F1 + c0);
            #pragma unroll
            for (int j = 0; j < 4; ++j)
                out[j] = make_float4(acc[r][4*j], acc[r][4*j+1], acc[r][4*j+2], acc[r][4*j+3]);
        }
    }
}

// Layer-1 aggregation (CSR gather, atomic-free) fused with self-term + relu.
// One warp per node; lane owns feature pair [2*lane, 2*lane+1].
__global__ __launch_bounds__(256) void agg1_kernel() {
    int warp = (blockIdx.x * 256 + threadIdx.x) >> 5;
    int lane = threadIdx.x & 31;
    if (warp >= NN) return;
    int node = warp;

    int beg = g_off[node];
    int end = g_off[node + 1];
    float inv_d = g_invsqrt[node];

    const float2* h1f = reinterpret_cast<const float2*>(g_h1);
    float2 a0 = make_float2(0.f, 0.f);
    float2 a1 = make_float2(0.f, 0.f);

    int e = beg;
    for (; e + 1 < end; e += 2) {
        int s0 = g_csr_src[e];
        int s1 = g_csr_src[e + 1];
        float n0 = g_invsqrt[s0] * inv_d;
        float n1 = g_invsqrt[s1] * inv_d;
        float2 v0 = h1f[(size_t)s0 * 32 + lane];
        float2 v1 = h1f[(size_t)s1 * 32 + lane];
        a0.x = fmaf(v0.x, n0, a0.x); a0.y = fmaf(v0.y, n0, a0.y);
        a1.x = fmaf(v1.x, n1, a1.x); a1.y = fmaf(v1.y, n1, a1.y);
    }
    if (e < end) {
        int s0 = g_csr_src[e];
        float n0 = g_invsqrt[s0] * inv_d;
        float2 v0 = h1f[(size_t)s0 * 32 + lane];
        a0.x = fmaf(v0.x, n0, a0.x); a0.y = fmaf(v0.y, n0, a0.y);
    }

    float id = inv_d * inv_d;
    float2 h = h1f[(size_t)node * 32 + lane];
    float2 o;
    o.x = fmaxf(fmaf(h.x, id, a0.x + a1.x), 0.f);
    o.y = fmaxf(fmaf(h.y, id, a0.y + a1.y), 0.f);
    reinterpret_cast<float2*>(g_out1)[(size_t)node * 32 + lane] = o;
}

// h2 = out1 @ W2 (64 -> 40). Thread per row, W2 in SMEM.
__global__ __launch_bounds__(256) void gemm2_kernel(const float* __restrict__ W2) {
    __shared__ float sW[F1 * F2];           // 10.25 KB
    int tid = threadIdx.x;
    for (int i = tid; i < F1 * F2; i += 256) sW[i] = W2[i];
    __syncthreads();

    int row = blockIdx.x * 256 + tid;
    if (row >= NN) return;

    float acc[F2];
    #pragma unroll
    for (int j = 0; j < F2; ++j) acc[j] = 0.f;

    const float4* orow = reinterpret_cast<const float4*>(g_out1 + (size_t)row * F1);
    #pragma unroll 2
    for (int k4 = 0; k4 < F1 / 4; ++k4) {
        float4 ov = orow[k4];
        float oa[4] = {ov.x, ov.y, ov.z, ov.w};
        #pragma unroll
        for (int kk = 0; kk < 4; ++kk) {
            float os = oa[kk];
            const float4* w4 = reinterpret_cast<const float4*>(sW + (k4 * 4 + kk) * F2);
            #pragma unroll
            for (int j = 0; j < F2 / 4; ++j) {
                float4 w = w4[j];
                acc[4*j+0] = fmaf(os, w.x, acc[4*j+0]);
                acc[4*j+1] = fmaf(os, w.y, acc[4*j+1]);
                acc[4*j+2] = fmaf(os, w.z, acc[4*j+2]);
                acc[4*j+3] = fmaf(os, w.w, acc[4*j+3]);
            }
        }
    }
    float4* out = reinterpret_cast<float4*>(g_h2 + (size_t)row * F2);
    #pragma unroll
    for (int j = 0; j < F2 / 4; ++j)
        out[j] = make_float4(acc[4*j], acc[4*j+1], acc[4*j+2], acc[4*j+3]);
}

// Layer-2 aggregation (CSR gather) fused with self-term + relu -> d_out.
// One warp per node; lane owns feature `lane`, and feature 32+lane if lane<8.
__global__ __launch_bounds__(256) void agg2_kernel(float* __restrict__ out) {
    int warp = (blockIdx.x * 256 + threadIdx.x) >> 5;
    int lane = threadIdx.x & 31;
    if (warp >= NN) return;
    int node = warp;

    int beg = g_off[node];
    int end = g_off[node + 1];
    float inv_d = g_invsqrt[node];
    bool hi = (lane < 8);

    float aa0 = 0.f, ab0 = 0.f;
    float aa1 = 0.f, ab1 = 0.f;

    int e = beg;
    for (; e + 1 < end; e += 2) {
        int s0 = g_csr_src[e];
        int s1 = g_csr_src[e + 1];
        float n0 = g_invsqrt[s0] * inv_d;
        float n1 = g_invsqrt[s1] * inv_d;
        const float* r0 = g_h2 + (size_t)s0 * F2;
        const float* r1 = g_h2 + (size_t)s1 * F2;
        float va0 = r0[lane];
        float va1 = r1[lane];
        float vb0 = hi ? r0[32 + lane] : 0.f;
        float vb1 = hi ? r1[32 + lane] : 0.f;
        aa0 = fmaf(va0, n0, aa0); ab0 = fmaf(vb0, n0, ab0);
        aa1 = fmaf(va1, n1, aa1); ab1 = fmaf(vb1, n1, ab1);
    }
    if (e < end) {
        int s0 = g_csr_src[e];
        float n0 = g_invsqrt[s0] * inv_d;
        const float* r0 = g_h2 + (size_t)s0 * F2;
        aa0 = fmaf(r0[lane], n0, aa0);
        if (hi) ab0 = fmaf(r0[32 + lane], n0, ab0);
    }

    float id = inv_d * inv_d;
    const float* hrow = g_h2 + (size_t)node * F2;
    float* orow = out + (size_t)node * F2;
    orow[lane] = fmaxf(fmaf(hrow[lane], id, aa0 + aa1), 0.f);
    if (hi)
        orow[32 + lane] = fmaxf(fmaf(hrow[32 + lane], id, ab0 + ab1), 0.f);
}

// ---------------- launch ----------------------------------------------------
extern "C" void kernel_launch(void* const* d_in, const int* in_sizes, int n_in,
                              void* d_out, int out_size) {
    const float* x  = (const float*)d_in[0];   // [N,128]
    const int*   ei = (const int*)  d_in[1];   // [2,E]
    const float* W1 = (const float*)d_in[2];   // [128,64]
    const float* W2 = (const float*)d_in[3];   // [64,40]
    float* out = (float*)d_out;

    int E = in_sizes[1] / 2;
    const int* src = ei;
    const int* dst = ei + E;

    // CSR build (by dst)
    zero_kernel  <<<(NN + 255) / 256, 256>>>();
    deg_kernel   <<<(E + 255) / 256, 256>>>(dst, E);
    prefix_kernel<<<1, 1024>>>();
    fill_kernel  <<<(E + 255) / 256, 256>>>(src, dst, E);
    invsqrt_kernel<<<(NN + 255) / 256, 256>>>();

    // layer 1
    gemm1_kernel <<<(NN + 127) / 128, 128>>>(x, W1);     // h1 = x @ W1
    agg1_kernel  <<<(NN * 32 + 255) / 256, 256>>>();     // out1 = relu(norm-agg + self)

    // layer 2
    gemm2_kernel <<<(NN + 255) / 256, 256>>>(W2);        // h2 = out1 @ W2
    agg2_kernel  <<<(NN * 32 + 255) / 256, 256>>>(out);  // out = relu(norm-agg + self)
}